// round 8
// baseline (speedup 1.0000x reference)
#include <cuda_runtime.h>
#include <cstdint>

#define BATCH 8192
#define NNEI  32
#define DIN   512
#define DHID  512
#define DOUT  512

// ---------------- device scratch (no allocs allowed) ----------------
__device__ __align__(1024) float g_pooled[BATCH * DHID];   // stored pre-rounded to tf32
__device__ __align__(1024) float g_wT[3 * 512 * 512];      // tf32-rounded, K-major [N,K]: mlp, neigh, self

// Compensation for HW truncation (round-toward-zero) of raw fp32 A operands.
#define TRUNC_COMP 1.000345f

// ---------------- helpers ----------------
__device__ __forceinline__ uint32_t f2tf(float x) {
    uint32_t r;
    asm("cvt.rna.tf32.f32 %0, %1;" : "=r"(r) : "f"(x));
    return r;
}

__device__ __forceinline__ uint32_t smem_u32(const void* p) {
    uint32_t a;
    asm("{ .reg .u64 t; cvta.to.shared.u64 t, %1; cvt.u32.u64 %0, t; }" : "=r"(a) : "l"(p));
    return a;
}

__device__ __forceinline__ uint32_t swz128(uint32_t b) { return b ^ ((b >> 3) & 0x70); }

__device__ __forceinline__ void cp_async16(uint32_t sdst, const float* gsrc) {
    asm volatile("cp.async.cg.shared.global [%0], [%1], 16;\n" :: "r"(sdst), "l"(gsrc));
}
#define CP_COMMIT() asm volatile("cp.async.commit_group;\n" ::: "memory")
#define CP_WAIT1()  asm volatile("cp.async.wait_group 1;\n" ::: "memory")

#define LDSM_X4(r0, r1, r2, r3, addr) \
    asm volatile("ldmatrix.sync.aligned.m8n8.x4.shared.b16 {%0,%1,%2,%3}, [%4];" \
        : "=r"(r0), "=r"(r1), "=r"(r2), "=r"(r3) : "r"(addr))

__device__ __forceinline__ void mma8(float* c,
                                     uint32_t a0, uint32_t a1, uint32_t a2, uint32_t a3,
                                     uint32_t b0, uint32_t b1) {
    asm volatile(
        "mma.sync.aligned.m16n8k8.row.col.f32.tf32.tf32.f32 "
        "{%0,%1,%2,%3},{%4,%5,%6,%7},{%8,%9},{%0,%1,%2,%3};\n"
        : "+f"(c[0]), "+f"(c[1]), "+f"(c[2]), "+f"(c[3])
        : "r"(a0), "r"(a1), "r"(a2), "r"(a3), "r"(b0), "r"(b1));
}

// ---------------- SMEM: 3 stages x 48KB (A 256x32 f32 @ +0, B 128x32 f32 @ +32768) ----
#define STAGE_BYTES 49152
#define B_OFF       32768
#define SMEM_TOTAL  (3 * STAGE_BYTES)   // 147456

// issue one K-chunk (32 wide) of A[256 rows] and Bt[128 n-rows] into a stage, SW128 swizzled
__device__ __forceinline__ void issue_chunk(const float* __restrict__ A,
                                            const float* __restrict__ Bt,
                                            int rowBase, int nBase, int kt,
                                            uint32_t stage, int tid) {
#pragma unroll
    for (int j = 0; j < 8; j++) {
        int pos = tid + j * 256;           // 256 rows x 8 (16B units)
        int r = pos >> 3, c = pos & 7;
        cp_async16(stage + swz128(r * 128 + c * 16),
                   A + (rowBase + r) * 512 + kt * 32 + c * 4);
    }
#pragma unroll
    for (int j = 0; j < 4; j++) {
        int pos = tid + j * 256;           // 128 n-rows x 8
        int r = pos >> 3, c = pos & 7;
        cp_async16(stage + B_OFF + swz128(r * 128 + c * 16),
                   Bt + (nBase + r) * 512 + kt * 32 + c * 4);
    }
}

// One K-chunk of MMAs for this warp's 64x64 tile (4 m-tiles x 8 n-tiles).
// A fragments fed RAW (HW tf32 truncation; compensated in weight prep).
__device__ __forceinline__ void compute_chunk(uint32_t aBase, uint32_t bBase,
                                              float c[4][8][4],
                                              int warpM, int warpN, int lane) {
    uint32_t xorv = (uint32_t)(lane & 7) << 4;
    uint32_t aRow = aBase + (warpM * 64 + (lane & 15)) * 128;
    uint32_t cA = (uint32_t)(lane >> 4) * 16;
    uint32_t bRow = bBase + (warpN * 64 + ((lane >> 4) & 1) * 8 + (lane & 7)) * 128;
    uint32_t cB = (uint32_t)((lane >> 3) & 1) * 16;

#pragma unroll
    for (int k8 = 0; k8 < 4; k8++) {
        uint32_t offA = (k8 * 32 + cA) ^ xorv;
        uint32_t offB = (k8 * 32 + cB) ^ xorv;
        uint32_t a[4][4];
#pragma unroll
        for (int mt = 0; mt < 4; mt++)
            LDSM_X4(a[mt][0], a[mt][1], a[mt][2], a[mt][3], aRow + mt * 2048 + offA);
        uint32_t b[8][2];
#pragma unroll
        for (int j = 0; j < 4; j++) {
            uint32_t b0, b1, b2, b3;
            LDSM_X4(b0, b1, b2, b3, bRow + j * 2048 + offB);
            b[2 * j][0] = b0;     b[2 * j][1] = b1;
            b[2 * j + 1][0] = b2; b[2 * j + 1][1] = b3;
        }
#pragma unroll
        for (int mt = 0; mt < 4; mt++)
#pragma unroll
            for (int nt = 0; nt < 8; nt++)
                mma8(c[mt][nt], a[mt][0], a[mt][1], a[mt][2], a[mt][3],
                     b[nt][0], b[nt][1]);
    }
}

// Shared 3-stage pipelined mainloop. sel(u) -> (A, Bt, kt).
template <int NCHUNK, typename SEL>
__device__ __forceinline__ void gemm_mainloop(SEL sel, int rowBase, int nBase,
                                              uint32_t sbase, float c[4][8][4],
                                              int tid, int warpM, int warpN, int lane) {
    {
        const float *A, *B; int kt;
        sel(0, A, B, kt); issue_chunk(A, B, rowBase, nBase, kt, sbase, tid); CP_COMMIT();
        sel(1, A, B, kt); issue_chunk(A, B, rowBase, nBase, kt, sbase + STAGE_BYTES, tid); CP_COMMIT();
    }
    uint32_t stage_off = 0;
    for (int u = 0; u < NCHUNK; u++) {
        CP_WAIT1();
        __syncthreads();
        if (u + 2 < NCHUNK) {
            const float *A, *B; int kt;
            sel(u + 2, A, B, kt);
            uint32_t so = stage_off + 2 * STAGE_BYTES;
            if (so >= 3 * STAGE_BYTES) so -= 3 * STAGE_BYTES;
            issue_chunk(A, B, rowBase, nBase, kt, sbase + so, tid);
        }
        CP_COMMIT();
        compute_chunk(sbase + stage_off, sbase + stage_off + B_OFF, c, warpM, warpN, lane);
        stage_off += STAGE_BYTES;
        if (stage_off == 3 * STAGE_BYTES) stage_off = 0;
    }
}

// ---------------- Kernel 1: h = neigh @ mlp_w; pooled = relu(max32(h) + b) ----------------
// grid (4, 1024): CTA tile 256(M) x 128(N); warp = 64x64; each warp = 2 pool groups.
__global__ void __launch_bounds__(256, 1)
k_mlp_maxpool(const float* __restrict__ neigh, const float* __restrict__ mlp_b) {
    extern __shared__ char sm[];
    int tid = threadIdx.x, warp = tid >> 5, lane = tid & 31;
    int g = lane >> 2, tig = lane & 3;
    int warpM = warp >> 1, warpN = warp & 1;     // 4 x 2
    int rowBase = blockIdx.y * 256;
    int nBase   = blockIdx.x * 128;
    uint32_t sbase = smem_u32(sm);

    float c[4][8][4];
#pragma unroll
    for (int mt = 0; mt < 4; mt++)
#pragma unroll
        for (int nt = 0; nt < 8; nt++)
#pragma unroll
            for (int i = 0; i < 4; i++) c[mt][nt][i] = 0.f;

    const float* wT = g_wT;
    auto sel = [&](int u, const float*& A, const float*& B, int& kt) {
        A = neigh; B = wT; kt = u;
    };
    gemm_mainloop<16>(sel, rowBase, nBase, sbase, c, tid, warpM, warpN, lane);

    // Epilogue: warp's 64 rows = pool groups {g0, g0+1}; store pooled pre-rounded to tf32.
    int group0 = (rowBase >> 5) + warpM * 2;
#pragma unroll
    for (int half = 0; half < 2; half++) {
        int group = group0 + half;
#pragma unroll
        for (int nt = 0; nt < 8; nt++) {
            int m0t = 2 * half, m1t = 2 * half + 1;
            float m0 = fmaxf(fmaxf(c[m0t][nt][0], c[m0t][nt][2]),
                             fmaxf(c[m1t][nt][0], c[m1t][nt][2]));
            float m1 = fmaxf(fmaxf(c[m0t][nt][1], c[m0t][nt][3]),
                             fmaxf(c[m1t][nt][1], c[m1t][nt][3]));
#pragma unroll
            for (int off = 4; off < 32; off <<= 1) {
                m0 = fmaxf(m0, __shfl_xor_sync(0xffffffffu, m0, off));
                m1 = fmaxf(m1, __shfl_xor_sync(0xffffffffu, m1, off));
            }
            if (g == 0) {
                int col = nBase + warpN * 64 + nt * 8 + 2 * tig;
                float p0 = fmaxf(m0 + mlp_b[col], 0.f);
                float p1 = fmaxf(m1 + mlp_b[col + 1], 0.f);
                g_pooled[group * DHID + col]     = __uint_as_float(f2tf(p0));
                g_pooled[group * DHID + col + 1] = __uint_as_float(f2tf(p1));
            }
        }
    }
}

// ---------------- Kernel 2: out = relu(pooled @ neigh_w + self @ self_w) ----------------
// grid (4, 32): CTA 256 x 128, virtual K = 1024.
__global__ void __launch_bounds__(256, 1)
k_out(const float* __restrict__ selfv, float* __restrict__ out) {
    extern __shared__ char sm[];
    int tid = threadIdx.x, warp = tid >> 5, lane = tid & 31;
    int g = lane >> 2, tig = lane & 3;
    int warpM = warp >> 1, warpN = warp & 1;
    int rowBase = blockIdx.y * 256;
    int nBase   = blockIdx.x * 128;
    uint32_t sbase = smem_u32(sm);

    float c[4][8][4];
#pragma unroll
    for (int mt = 0; mt < 4; mt++)
#pragma unroll
        for (int nt = 0; nt < 8; nt++)
#pragma unroll
            for (int i = 0; i < 4; i++) c[mt][nt][i] = 0.f;

    const float* neigh_wT = g_wT + 512 * 512;
    const float* self_wT  = g_wT + 2 * 512 * 512;
    auto sel = [&](int u, const float*& A, const float*& B, int& kt) {
        if (u < 16) { A = g_pooled; B = neigh_wT; } else { A = selfv; B = self_wT; }
        kt = u & 15;
    };
    gemm_mainloop<32>(sel, rowBase, nBase, sbase, c, tid, warpM, warpN, lane);

#pragma unroll
    for (int mt = 0; mt < 4; mt++) {
#pragma unroll
        for (int nt = 0; nt < 8; nt++) {
            int row = rowBase + warpM * 64 + mt * 16 + g;
            int col = nBase + warpN * 64 + nt * 8 + 2 * tig;
            float2 v0 = make_float2(fmaxf(c[mt][nt][0], 0.f), fmaxf(c[mt][nt][1], 0.f));
            float2 v1 = make_float2(fmaxf(c[mt][nt][2], 0.f), fmaxf(c[mt][nt][3], 0.f));
            *reinterpret_cast<float2*>(out + row * DOUT + col)       = v0;
            *reinterpret_cast<float2*>(out + (row + 8) * DOUT + col) = v1;
        }
    }
}

// ---------------- Weight transpose + compensate + tf32 pre-round: [K,N] -> K-major [N,K] ----
__global__ void __launch_bounds__(256)
k_transpose(const float* __restrict__ w0, const float* __restrict__ w1,
            const float* __restrict__ w2) {
    const float* src = (blockIdx.z == 0) ? w0 : (blockIdx.z == 1) ? w1 : w2;
    // mlp_w (z=0) and self_w (z=2) pair with truncated raw-fp32 A -> compensate.
    // neigh_w (z=1) pairs with pre-rounded tf32 pooled -> exact.
    float scale = (blockIdx.z == 1) ? 1.0f : TRUNC_COMP;
    float* dst = g_wT + blockIdx.z * (512 * 512);
    __shared__ float t[32][33];
    int bx = blockIdx.x * 32, by = blockIdx.y * 32;
    int tx = threadIdx.x & 31, ty = threadIdx.x >> 5;
#pragma unroll
    for (int i = 0; i < 4; i++)
        t[ty + i * 8][tx] = src[(by + ty + i * 8) * 512 + bx + tx];
    __syncthreads();
#pragma unroll
    for (int i = 0; i < 4; i++)
        dst[(bx + ty + i * 8) * 512 + by + tx] = __uint_as_float(f2tf(t[tx][ty + i * 8] * scale));
}

extern "C" void kernel_launch(void* const* d_in, const int* in_sizes, int n_in,
                              void* d_out, int out_size) {
    const float* selfv   = (const float*)d_in[0];
    const float* neigh   = (const float*)d_in[1];
    const float* mlp_w   = (const float*)d_in[2];
    const float* mlp_b   = (const float*)d_in[3];
    const float* neigh_w = (const float*)d_in[4];
    const float* self_w  = (const float*)d_in[5];
    float* out = (float*)d_out;

    cudaFuncSetAttribute(k_mlp_maxpool, cudaFuncAttributeMaxDynamicSharedMemorySize, SMEM_TOTAL);
    cudaFuncSetAttribute(k_out,         cudaFuncAttributeMaxDynamicSharedMemorySize, SMEM_TOTAL);

    k_transpose<<<dim3(16, 16, 3), 256>>>(mlp_w, neigh_w, self_w);

    dim3 grid1(DHID / 128, (BATCH * NNEI) / 256);   // (4, 1024)
    k_mlp_maxpool<<<grid1, 256, SMEM_TOTAL>>>(neigh, mlp_b);

    dim3 grid2(DOUT / 128, BATCH / 256);            // (4, 32)
    k_out<<<grid2, 256, SMEM_TOTAL>>>(selfv, out);
}